// round 1
// baseline (speedup 1.0000x reference)
#include <cuda_runtime.h>
#include <cuda_fp16.h>
#include <cstdint>

// ---------------------------------------------------------------------------
// Fused LSTM cell, fp16 tensor-core (mma.sync) implementation.
//   gates = [x|h_] @ W^T + b   (W stacked [4C, I+H] = [512, 256], gate-interleaved)
//   c = sigm(gf)*c_ + sigm(gi)*tanh(gz);  h = sigm(go)*tanh(c)
//   y = sigm(h @ w_out^T + b_out)
// Outputs concatenated in d_out as [c | h | y], each B*128 fp32.
// ---------------------------------------------------------------------------

#define LDA1 264   // half stride for 256-wide tiles (+8 pad)
#define LDA2 136   // half stride for 128-wide tiles (+8 pad)

__device__ __half g_W16r[512 * 256];    // reordered stacked gate weights, fp16
__device__ __half g_wout16[128 * 128];  // w_out, fp16

// ---------------------------------------------------------------------------
// K0: convert + reorder weights.
// Gate-interleave layout: for chunk in 0..3 (32 gate-cols each),
//   rows [chunk*128 .. +128) = [grp0: z0-15,i0-15,f0-15,o0-15, grp1: z16-31,...]
// so each N-warp (64 cols) holds matched z/i/f/o columns in its accumulators.
// ---------------------------------------------------------------------------
__global__ void prep_weights(const float* __restrict__ w,  const float* __restrict__ wi,
                             const float* __restrict__ wf, const float* __restrict__ wo,
                             const float* __restrict__ w_out)
{
    for (int idx = blockIdx.x * blockDim.x + threadIdx.x; idx < 512 * 256;
         idx += gridDim.x * blockDim.x) {
        int dstrow = idx >> 8;
        int k      = idx & 255;
        int chunk  = dstrow >> 7;
        int r      = dstrow & 127;
        int grp    = r >> 6;
        int gate   = (r >> 4) & 3;
        int sub    = r & 15;
        int gc     = chunk * 32 + grp * 16 + sub;   // original gate-column index
        const float* src = (gate == 0) ? w : (gate == 1) ? wi : (gate == 2) ? wf : wo;
        g_W16r[idx] = __float2half_rn(src[gc * 256 + k]);
    }
    for (int idx = blockIdx.x * blockDim.x + threadIdx.x; idx < 128 * 128;
         idx += gridDim.x * blockDim.x) {
        g_wout16[idx] = __float2half_rn(w_out[idx]);
    }
}

// ---------------------------------------------------------------------------
// mma.sync helpers
// ---------------------------------------------------------------------------
__device__ __forceinline__ void ldsm_x4(uint32_t addr, uint32_t& r0, uint32_t& r1,
                                        uint32_t& r2, uint32_t& r3)
{
    asm volatile("ldmatrix.sync.aligned.m8n8.x4.shared.b16 {%0,%1,%2,%3}, [%4];"
                 : "=r"(r0), "=r"(r1), "=r"(r2), "=r"(r3) : "r"(addr));
}

__device__ __forceinline__ void mma16816(float* c, uint32_t a0, uint32_t a1, uint32_t a2,
                                         uint32_t a3, uint32_t b0, uint32_t b1)
{
    asm volatile(
        "mma.sync.aligned.m16n8k16.row.col.f32.f16.f16.f32 "
        "{%0,%1,%2,%3},{%4,%5,%6,%7},{%8,%9},{%0,%1,%2,%3};"
        : "+f"(c[0]), "+f"(c[1]), "+f"(c[2]), "+f"(c[3])
        : "r"(a0), "r"(a1), "r"(a2), "r"(a3), "r"(b0), "r"(b1));
}

__device__ __forceinline__ float fsigmoid(float v) { return 0.5f * tanhf(0.5f * v) + 0.5f; }

extern __shared__ __half smem[];

// ---------------------------------------------------------------------------
// K1: gates GEMM (M=128/CTA, N=512 in 4 chunks of 128, K=256) + LSTM epilogue.
// 256 threads = 8 warps in 4(M) x 2(N) grid; warp tile 32x64.
// ---------------------------------------------------------------------------
__global__ __launch_bounds__(256, 1) void lstm_gemm1(
    const float* __restrict__ x, const float* __restrict__ h_,
    const float* __restrict__ c_,
    const float* __restrict__ b,  const float* __restrict__ bi,
    const float* __restrict__ bf, const float* __restrict__ bo,
    float* __restrict__ outC, float* __restrict__ outH)
{
    __half* As = smem;               // [128][LDA1] fp16 xh tile
    __half* Bs = smem + 128 * LDA1;  // [128][LDA1] fp16 weight chunk

    const int tid  = threadIdx.x;
    const int row0 = blockIdx.x * 128;

    // Load + convert xh tile: cols 0-127 = x, 128-255 = h_
    for (int i = tid; i < 128 * 64; i += 256) {
        int row = i >> 6, q = i & 63;
        const float* src = (q < 32) ? (x  + (size_t)(row0 + row) * 128 + q * 4)
                                    : (h_ + (size_t)(row0 + row) * 128 + (q - 32) * 4);
        float4 v = *(const float4*)src;
        __half2* dst = (__half2*)(As + row * LDA1 + q * 4);
        dst[0] = __floats2half2_rn(v.x, v.y);
        dst[1] = __floats2half2_rn(v.z, v.w);
    }

    const uint32_t As_base = (uint32_t)__cvta_generic_to_shared(As);
    const uint32_t Bs_base = (uint32_t)__cvta_generic_to_shared(Bs);
    const int warp  = tid >> 5, lane = tid & 31;
    const int warpM = warp >> 1, warpN = warp & 1;

    // ldmatrix per-lane address components
    const int a_row  = warpM * 32 + (lane & 15);
    const int a_koff = (lane >> 4) << 3;
    const int b_nloc = ((lane >> 4) & 1) * 8 + (lane & 7);
    const int b_koff = ((lane >> 3) & 1) * 8;

    __syncthreads();

    for (int chunk = 0; chunk < 4; chunk++) {
        // Stream this chunk's 128 reordered gate rows (64KB) from L2
        for (int i = tid; i < 128 * 32; i += 256) {
            int row = i >> 5, seg = i & 31;
            *(uint4*)(Bs + row * LDA1 + seg * 8) =
                *(const uint4*)(g_W16r + (size_t)(chunk * 128 + row) * 256 + seg * 8);
        }
        __syncthreads();

        float acc[2][8][4];
        #pragma unroll
        for (int mt = 0; mt < 2; mt++)
            #pragma unroll
            for (int nt = 0; nt < 8; nt++)
                #pragma unroll
                for (int r = 0; r < 4; r++) acc[mt][nt][r] = 0.f;

        #pragma unroll
        for (int ks = 0; ks < 16; ks++) {
            const int k0 = ks * 16;
            uint32_t a[2][4];
            #pragma unroll
            for (int mt = 0; mt < 2; mt++) {
                uint32_t addr = As_base + (uint32_t)(((a_row + mt * 16) * LDA1 + k0 + a_koff) * 2);
                ldsm_x4(addr, a[mt][0], a[mt][1], a[mt][2], a[mt][3]);
            }
            uint32_t bb[4][4];
            #pragma unroll
            for (int ntp = 0; ntp < 4; ntp++) {
                uint32_t addr = Bs_base +
                    (uint32_t)(((warpN * 64 + ntp * 16 + b_nloc) * LDA1 + k0 + b_koff) * 2);
                ldsm_x4(addr, bb[ntp][0], bb[ntp][1], bb[ntp][2], bb[ntp][3]);
            }
            #pragma unroll
            for (int nt = 0; nt < 8; nt++) {
                const int ntp = nt >> 1, hi = nt & 1;
                #pragma unroll
                for (int mt = 0; mt < 2; mt++)
                    mma16816(acc[mt][nt], a[mt][0], a[mt][1], a[mt][2], a[mt][3],
                             bb[ntp][hi * 2], bb[ntp][hi * 2 + 1]);
            }
        }
        __syncthreads();  // all MMA reads of Bs done before next chunk overwrite

        // Register-only epilogue: nt = 2*gate + p holds matching z/i/f/o columns
        #pragma unroll
        for (int mt = 0; mt < 2; mt++) {
            #pragma unroll
            for (int rh = 0; rh < 2; rh++) {
                const int row = row0 + warpM * 32 + mt * 16 + (lane >> 2) + rh * 8;
                #pragma unroll
                for (int p = 0; p < 2; p++) {
                    #pragma unroll
                    for (int e = 0; e < 2; e++) {
                        const int col = chunk * 32 + warpN * 16 + p * 8 + 2 * (lane & 3) + e;
                        const int ri  = rh * 2 + e;
                        float gz = acc[mt][0 + p][ri] + __ldg(b  + col);
                        float gi = acc[mt][2 + p][ri] + __ldg(bi + col);
                        float gf = acc[mt][4 + p][ri] + __ldg(bf + col);
                        float go = acc[mt][6 + p][ri] + __ldg(bo + col);
                        float z  = tanhf(gz);
                        float si = fsigmoid(gi);
                        float sf = fsigmoid(gf);
                        float so = fsigmoid(go);
                        float cold = __ldg(c_ + (size_t)row * 128 + col);
                        float cnew = sf * cold + si * z;
                        float hh   = so * tanhf(cnew);
                        outC[(size_t)row * 128 + col] = cnew;
                        outH[(size_t)row * 128 + col] = hh;
                    }
                }
            }
        }
    }
}

// ---------------------------------------------------------------------------
// K2: y = sigmoid(h @ w_out^T + b_out).  M=128/CTA, N=128, K=128.
// ---------------------------------------------------------------------------
__global__ __launch_bounds__(256, 1) void lstm_gemm2(
    const float* __restrict__ hsrc, const float* __restrict__ b_out,
    float* __restrict__ outY)
{
    __half* As = smem;               // [128][LDA2]
    __half* Bs = smem + 128 * LDA2;  // [128][LDA2]

    const int tid  = threadIdx.x;
    const int row0 = blockIdx.x * 128;

    for (int i = tid; i < 128 * 32; i += 256) {
        int row = i >> 5, q = i & 31;
        float4 v = *(const float4*)(hsrc + (size_t)(row0 + row) * 128 + q * 4);
        __half2* dst = (__half2*)(As + row * LDA2 + q * 4);
        dst[0] = __floats2half2_rn(v.x, v.y);
        dst[1] = __floats2half2_rn(v.z, v.w);
    }
    for (int i = tid; i < 128 * 16; i += 256) {
        int row = i >> 4, seg = i & 15;
        *(uint4*)(Bs + row * LDA2 + seg * 8) =
            *(const uint4*)(g_wout16 + (size_t)row * 128 + seg * 8);
    }

    const uint32_t As_base = (uint32_t)__cvta_generic_to_shared(As);
    const uint32_t Bs_base = (uint32_t)__cvta_generic_to_shared(Bs);
    const int warp  = tid >> 5, lane = tid & 31;
    const int warpM = warp >> 1, warpN = warp & 1;

    const int a_row  = warpM * 32 + (lane & 15);
    const int a_koff = (lane >> 4) << 3;
    const int b_nloc = ((lane >> 4) & 1) * 8 + (lane & 7);
    const int b_koff = ((lane >> 3) & 1) * 8;

    __syncthreads();

    float acc[2][8][4];
    #pragma unroll
    for (int mt = 0; mt < 2; mt++)
        #pragma unroll
        for (int nt = 0; nt < 8; nt++)
            #pragma unroll
            for (int r = 0; r < 4; r++) acc[mt][nt][r] = 0.f;

    #pragma unroll
    for (int ks = 0; ks < 8; ks++) {
        const int k0 = ks * 16;
        uint32_t a[2][4];
        #pragma unroll
        for (int mt = 0; mt < 2; mt++) {
            uint32_t addr = As_base + (uint32_t)(((a_row + mt * 16) * LDA2 + k0 + a_koff) * 2);
            ldsm_x4(addr, a[mt][0], a[mt][1], a[mt][2], a[mt][3]);
        }
        uint32_t bb[4][4];
        #pragma unroll
        for (int ntp = 0; ntp < 4; ntp++) {
            uint32_t addr = Bs_base +
                (uint32_t)(((warpN * 64 + ntp * 16 + b_nloc) * LDA2 + k0 + b_koff) * 2);
            ldsm_x4(addr, bb[ntp][0], bb[ntp][1], bb[ntp][2], bb[ntp][3]);
        }
        #pragma unroll
        for (int nt = 0; nt < 8; nt++) {
            const int ntp = nt >> 1, hi = nt & 1;
            #pragma unroll
            for (int mt = 0; mt < 2; mt++)
                mma16816(acc[mt][nt], a[mt][0], a[mt][1], a[mt][2], a[mt][3],
                         bb[ntp][hi * 2], bb[ntp][hi * 2 + 1]);
        }
    }

    #pragma unroll
    for (int mt = 0; mt < 2; mt++) {
        #pragma unroll
        for (int nt = 0; nt < 8; nt++) {
            #pragma unroll
            for (int rh = 0; rh < 2; rh++) {
                const int row = row0 + warpM * 32 + mt * 16 + (lane >> 2) + rh * 8;
                #pragma unroll
                for (int e = 0; e < 2; e++) {
                    const int col = warpN * 64 + nt * 8 + 2 * (lane & 3) + e;
                    float u = acc[mt][nt][rh * 2 + e] + __ldg(b_out + col);
                    outY[(size_t)row * 128 + col] = fsigmoid(u);
                }
            }
        }
    }
}

// ---------------------------------------------------------------------------
// Launch
// ---------------------------------------------------------------------------
extern "C" void kernel_launch(void* const* d_in, const int* in_sizes, int n_in,
                              void* d_out, int out_size)
{
    const float* c_    = (const float*)d_in[0];
    const float* h_    = (const float*)d_in[1];
    const float* x     = (const float*)d_in[2];
    const float* w     = (const float*)d_in[3];
    const float* wi    = (const float*)d_in[4];
    const float* wf    = (const float*)d_in[5];
    const float* wo    = (const float*)d_in[6];
    // d_in[7] = w_out
    const float* b     = (const float*)d_in[8];
    const float* bi    = (const float*)d_in[9];
    const float* bf    = (const float*)d_in[10];
    const float* bo    = (const float*)d_in[11];
    const float* b_out = (const float*)d_in[12];
    const float* w_out = (const float*)d_in[7];

    const int B  = in_sizes[0] / 128;   // rows (c_ has B*C elements, C=128)
    const size_t BC = (size_t)B * 128;

    float* outC = (float*)d_out;
    float* outH = outC + BC;
    float* outY = outH + BC;

    const int smem1 = 2 * 128 * LDA1 * (int)sizeof(__half);  // 135168
    const int smem2 = 2 * 128 * LDA2 * (int)sizeof(__half);  //  69632
    cudaFuncSetAttribute(lstm_gemm1, cudaFuncAttributeMaxDynamicSharedMemorySize, smem1);
    cudaFuncSetAttribute(lstm_gemm2, cudaFuncAttributeMaxDynamicSharedMemorySize, smem2);

    prep_weights<<<64, 256>>>(w, wi, wf, wo, w_out);
    lstm_gemm1<<<B / 128, 256, smem1>>>(x, h_, c_, b, bi, bf, bo, outC, outH);
    lstm_gemm2<<<B / 128, 256, smem2>>>(outH, b_out, outY);
}

// round 3
// speedup vs baseline: 1.5759x; 1.5759x over previous
#include <cuda_runtime.h>
#include <cuda_fp16.h>
#include <cstdint>

// ===========================================================================
// Fused LSTM cell, single-kernel mma.sync (legacy HMMA) implementation.
//   gates = [x|h_] @ W^T + bias ; c = sig(gf)*c_ + sig(gi)*tanh(gz)
//   h = sig(go)*tanh(c) ; y = sigmoid(h @ w_out^T + b_out)
// d_out = [c | h | y], each B*128 fp32.
// One CTA = 128 batch rows; gates GEMM in 8 N-chunks of 64 (cp.async double
// buffered), register-only LSTM epilogue, h kept in smem fp16, output GEMM
// fused in the same CTA.
// ===========================================================================

#define LDA 264   // halves: stride for 256-wide K tiles (+8 pad)
#define LDH 136   // halves: stride for 128-wide K tiles (+8 pad)

// byte offsets in dynamic smem
#define AS_OFF    0
#define BS_OFF(i) (67584 + (i) * 33792)
#define WOUT_OFF  135168
#define HT_OFF    169984
#define SMEM_TOT  204800

__device__ __half g_W16r[512 * 256];    // gate-interleaved stacked weights, fp16
__device__ __half g_wout16[128 * 128];  // w_out, fp16

// --------------------------------------------------------------------------
// K0: convert weights. Gate interleave for N-chunks of 64:
//   chunk k (0..7): 64 rows = [warpN0: z(8),i(8),f(8),o(8) | warpN1: same]
//   row r: grp=r>>5, gate=(r>>3)&3, sub=r&7 -> gate-col = k*16 + grp*8 + sub
// --------------------------------------------------------------------------
__global__ void prep_weights(const float* __restrict__ w,  const float* __restrict__ wi,
                             const float* __restrict__ wf, const float* __restrict__ wo,
                             const float* __restrict__ w_out)
{
    for (int idx = blockIdx.x * blockDim.x + threadIdx.x; idx < 512 * 256;
         idx += gridDim.x * blockDim.x) {
        int dstrow = idx >> 8, kk = idx & 255;
        int chunk = dstrow >> 6, r = dstrow & 63;
        int grp = r >> 5, gate = (r >> 3) & 3, sub = r & 7;
        int gc = chunk * 16 + grp * 8 + sub;
        const float* src = (gate == 0) ? w : (gate == 1) ? wi : (gate == 2) ? wf : wo;
        g_W16r[idx] = __float2half_rn(src[gc * 256 + kk]);
    }
    for (int idx = blockIdx.x * blockDim.x + threadIdx.x; idx < 128 * 128;
         idx += gridDim.x * blockDim.x)
        g_wout16[idx] = __float2half_rn(w_out[idx]);
}

// --------------------------------------------------------------------------
// helpers
// --------------------------------------------------------------------------
__device__ __forceinline__ void ldsm_x4(uint32_t addr, uint32_t& r0, uint32_t& r1,
                                        uint32_t& r2, uint32_t& r3)
{
    asm volatile("ldmatrix.sync.aligned.m8n8.x4.shared.b16 {%0,%1,%2,%3}, [%4];"
                 : "=r"(r0), "=r"(r1), "=r"(r2), "=r"(r3) : "r"(addr));
}
__device__ __forceinline__ void mma16816(float* c, const uint32_t* a, uint32_t b0, uint32_t b1)
{
    asm volatile(
        "mma.sync.aligned.m16n8k16.row.col.f32.f16.f16.f32 "
        "{%0,%1,%2,%3},{%4,%5,%6,%7},{%8,%9},{%0,%1,%2,%3};"
        : "+f"(c[0]), "+f"(c[1]), "+f"(c[2]), "+f"(c[3])
        : "r"(a[0]), "r"(a[1]), "r"(a[2]), "r"(a[3]), "r"(b0), "r"(b1));
}
__device__ __forceinline__ void cp16(uint32_t dst, const void* src)
{
    asm volatile("cp.async.cg.shared.global [%0], [%1], 16;" :: "r"(dst), "l"(src) : "memory");
}
__device__ __forceinline__ float tanha(float x) {
    float y; asm("tanh.approx.f32 %0, %1;" : "=f"(y) : "f"(x)); return y;
}
__device__ __forceinline__ float siga(float x) { return fmaf(tanha(0.5f * x), 0.5f, 0.5f); }

__device__ __forceinline__ uint4 pack8(float4 a, float4 b) {
    __half2 h0 = __floats2half2_rn(a.x, a.y), h1 = __floats2half2_rn(a.z, a.w);
    __half2 h2 = __floats2half2_rn(b.x, b.y), h3 = __floats2half2_rn(b.z, b.w);
    uint4 r;
    r.x = *(uint32_t*)&h0; r.y = *(uint32_t*)&h1;
    r.z = *(uint32_t*)&h2; r.w = *(uint32_t*)&h3;
    return r;
}

extern __shared__ char smem[];

// --------------------------------------------------------------------------
// Fused kernel. 256 threads = 8 warps in 4(M) x 2(N).
// --------------------------------------------------------------------------
__global__ __launch_bounds__(256, 1) void lstm_fused(
    const float* __restrict__ x, const float* __restrict__ h_,
    const float* __restrict__ c_,
    const float* __restrict__ bz, const float* __restrict__ bi,
    const float* __restrict__ bf, const float* __restrict__ bo,
    const float* __restrict__ bout,
    float* __restrict__ outC, float* __restrict__ outH, float* __restrict__ outY)
{
    const int tid  = threadIdx.x, lane = tid & 31;
    const int warp = tid >> 5;
    const int warpM = warp >> 1, warpN = warp & 1;
    const int row0 = blockIdx.x * 128;

    const uint32_t sbase = (uint32_t)__cvta_generic_to_shared(smem);

    // ---- async loads: w_out tile (group 0), weight chunk 0 (group 1) ----
    for (int i = tid; i < 2048; i += 256) {            // w_out: 128 x 256B rows
        int r = i >> 4, seg = i & 15;
        cp16(sbase + WOUT_OFF + (r * LDH + seg * 8) * 2, g_wout16 + r * 128 + seg * 8);
    }
    asm volatile("cp.async.commit_group;" ::: "memory");
    for (int i = tid; i < 2048; i += 256) {            // chunk 0: 64 x 512B rows
        int r = i >> 5, seg = i & 31;
        cp16(sbase + BS_OFF(0) + (r * LDA + seg * 8) * 2, g_W16r + r * 256 + seg * 8);
    }
    asm volatile("cp.async.commit_group;" ::: "memory");

    // ---- As: xh fp32 -> fp16 (cols 0-127 = x, 128-255 = h_) ----
    for (int i = tid; i < 128 * 64; i += 256) {
        int r = i >> 6, q = i & 63;                    // q indexes 4-float groups
        const float* src = (q < 32) ? (x  + (size_t)(row0 + r) * 128 + q * 4)
                                    : (h_ + (size_t)(row0 + r) * 128 + (q - 32) * 4);
        float4 v = *(const float4*)src;
        __half2* dst = (__half2*)(smem + AS_OFF + (r * LDA + q * 4) * 2);
        dst[0] = __floats2half2_rn(v.x, v.y);
        dst[1] = __floats2half2_rn(v.z, v.w);
    }

    // ldmatrix lane address components
    const int a_row  = warpM * 32 + (lane & 15);
    const int a_koff = (lane >> 4) << 3;
    const int b_nloc = ((lane >> 4) & 1) * 8 + (lane & 7);
    const int b_koff = ((lane >> 3) & 1) * 8;

    __half2* htile = (__half2*)(smem + HT_OFF);

    // =================== GEMM1 + LSTM epilogue, 8 chunks ===================
    #pragma unroll
    for (int c = 0; c < 8; c++) {
        __syncthreads();   // prior readers of buf[(c+1)&1] done; As ready at c=0
        if (c < 7) {
            const int nb = (c + 1) & 1;
            for (int i = tid; i < 2048; i += 256) {
                int r = i >> 5, seg = i & 31;
                cp16(sbase + BS_OFF(nb) + (r * LDA + seg * 8) * 2,
                     g_W16r + (size_t)(c + 1) * 16384 + r * 256 + seg * 8);
            }
            asm volatile("cp.async.commit_group;" ::: "memory");
            asm volatile("cp.async.wait_group 1;" ::: "memory");
        } else {
            asm volatile("cp.async.wait_group 0;" ::: "memory");
        }
        __syncthreads();   // chunk c visible to all warps

        float acc[2][4][4];
        #pragma unroll
        for (int mt = 0; mt < 2; mt++)
            #pragma unroll
            for (int nt = 0; nt < 4; nt++)
                #pragma unroll
                for (int r = 0; r < 4; r++) acc[mt][nt][r] = 0.f;

        const uint32_t as0 = sbase + AS_OFF;
        const uint32_t bs0 = sbase + BS_OFF(c & 1);
        #pragma unroll
        for (int ks = 0; ks < 16; ks++) {
            const int k0 = ks * 16;
            uint32_t a[2][4];
            #pragma unroll
            for (int mt = 0; mt < 2; mt++)
                ldsm_x4(as0 + (uint32_t)(((a_row + mt * 16) * LDA + k0 + a_koff) * 2),
                        a[mt][0], a[mt][1], a[mt][2], a[mt][3]);
            uint32_t bb[2][4];
            #pragma unroll
            for (int ntp = 0; ntp < 2; ntp++)
                ldsm_x4(bs0 + (uint32_t)(((warpN * 32 + ntp * 16 + b_nloc) * LDA + k0 + b_koff) * 2),
                        bb[ntp][0], bb[ntp][1], bb[ntp][2], bb[ntp][3]);
            #pragma unroll
            for (int nt = 0; nt < 4; nt++) {           // nt = gate (z,i,f,o)
                const int ntp = nt >> 1, hi = nt & 1;
                #pragma unroll
                for (int mt = 0; mt < 2; mt++)
                    mma16816(acc[mt][nt], a[mt], bb[ntp][hi * 2], bb[ntp][hi * 2 + 1]);
            }
        }

        // ---- register-only LSTM epilogue for this chunk's 16 gate-cols ----
        const int colb = c * 16 + warpN * 8 + 2 * (lane & 3);
        const float2 vz = __ldg((const float2*)(bz + colb));
        const float2 vi = __ldg((const float2*)(bi + colb));
        const float2 vf = __ldg((const float2*)(bf + colb));
        const float2 vo = __ldg((const float2*)(bo + colb));
        #pragma unroll
        for (int mt = 0; mt < 2; mt++) {
            #pragma unroll
            for (int rh = 0; rh < 2; rh++) {
                const int rloc = warpM * 32 + mt * 16 + (lane >> 2) + rh * 8;
                const int row  = row0 + rloc;
                const float2 cold = __ldg((const float2*)(c_ + (size_t)row * 128 + colb));
                float cn[2], hn[2];
                #pragma unroll
                for (int e = 0; e < 2; e++) {
                    const int ri = rh * 2 + e;
                    float gz = acc[mt][0][ri] + (e ? vz.y : vz.x);
                    float gi = acc[mt][1][ri] + (e ? vi.y : vi.x);
                    float gf = acc[mt][2][ri] + (e ? vf.y : vf.x);
                    float go = acc[mt][3][ri] + (e ? vo.y : vo.x);
                    float cc = fmaf(siga(gf), e ? cold.y : cold.x, siga(gi) * tanha(gz));
                    cn[e] = cc;
                    hn[e] = siga(go) * tanha(cc);
                }
                *(float2*)(outC + (size_t)row * 128 + colb) = make_float2(cn[0], cn[1]);
                *(float2*)(outH + (size_t)row * 128 + colb) = make_float2(hn[0], hn[1]);
                htile[(rloc * LDH + colb) >> 1] = __floats2half2_rn(hn[0], hn[1]);
            }
        }
    }

    __syncthreads();   // htile complete

    // =================== GEMM2: y = sigmoid(h @ w_out^T + b_out) ==========
    float acc2[2][8][4];
    #pragma unroll
    for (int mt = 0; mt < 2; mt++)
        #pragma unroll
        for (int nt = 0; nt < 8; nt++)
            #pragma unroll
            for (int r = 0; r < 4; r++) acc2[mt][nt][r] = 0.f;

    const uint32_t ht0 = sbase + HT_OFF;
    const uint32_t wo0 = sbase + WOUT_OFF;
    #pragma unroll
    for (int ks = 0; ks < 8; ks++) {
        const int k0 = ks * 16;
        uint32_t a[2][4];
        #pragma unroll
        for (int mt = 0; mt < 2; mt++)
            ldsm_x4(ht0 + (uint32_t)(((a_row + mt * 16) * LDH + k0 + a_koff) * 2),
                    a[mt][0], a[mt][1], a[mt][2], a[mt][3]);
        uint32_t bb[4][4];
        #pragma unroll
        for (int ntp = 0; ntp < 4; ntp++)
            ldsm_x4(wo0 + (uint32_t)(((warpN * 64 + ntp * 16 + b_nloc) * LDH + k0 + b_koff) * 2),
                    bb[ntp][0], bb[ntp][1], bb[ntp][2], bb[ntp][3]);
        #pragma unroll
        for (int nt = 0; nt < 8; nt++) {
            const int ntp = nt >> 1, hi = nt & 1;
            #pragma unroll
            for (int mt = 0; mt < 2; mt++)
                mma16816(acc2[mt][nt], a[mt], bb[ntp][hi * 2], bb[ntp][hi * 2 + 1]);
        }
    }

    #pragma unroll
    for (int nt = 0; nt < 8; nt++) {
        const int col = warpN * 64 + nt * 8 + 2 * (lane & 3);
        const float2 vb = __ldg((const float2*)(bout + col));
        #pragma unroll
        for (int mt = 0; mt < 2; mt++) {
            #pragma unroll
            for (int rh = 0; rh < 2; rh++) {
                const int row = row0 + warpM * 32 + mt * 16 + (lane >> 2) + rh * 8;
                float2 v;
                v.x = siga(acc2[mt][nt][rh * 2 + 0] + vb.x);
                v.y = siga(acc2[mt][nt][rh * 2 + 1] + vb.y);
                *(float2*)(outY + (size_t)row * 128 + col) = v;
            }
        }
    }
}

// --------------------------------------------------------------------------
// Launch
// --------------------------------------------------------------------------
extern "C" void kernel_launch(void* const* d_in, const int* in_sizes, int n_in,
                              void* d_out, int out_size)
{
    const float* c_    = (const float*)d_in[0];
    const float* h_    = (const float*)d_in[1];
    const float* x     = (const float*)d_in[2];
    const float* w     = (const float*)d_in[3];
    const float* wi    = (const float*)d_in[4];
    const float* wf    = (const float*)d_in[5];
    const float* wo    = (const float*)d_in[6];
    const float* w_out = (const float*)d_in[7];
    const float* b     = (const float*)d_in[8];
    const float* bi    = (const float*)d_in[9];
    const float* bf    = (const float*)d_in[10];
    const float* bo    = (const float*)d_in[11];
    const float* b_out = (const float*)d_in[12];

    const int B = in_sizes[0] / 128;
    const size_t BC = (size_t)B * 128;
    float* outC = (float*)d_out;
    float* outH = outC + BC;
    float* outY = outH + BC;

    cudaFuncSetAttribute(lstm_fused, cudaFuncAttributeMaxDynamicSharedMemorySize, SMEM_TOT);

    prep_weights<<<64, 256>>>(w, wi, wf, wo, w_out);
    lstm_fused<<<B / 128, 256, SMEM_TOT>>>(x, h_, c_, b, bi, bf, bo, b_out,
                                           outC, outH, outY);
}